// round 13
// baseline (speedup 1.0000x reference)
#include <cuda_runtime.h>
#include <cuda_bf16.h>
#include <math.h>
#include <stdint.h>

// B=4, CIN=64, HID=64, H=W=64, K=3, N=9, D=256, INC=128, OUTC=256
// HW=4096, CN = INC*9 = 1152 ; k-order: k = n*128 + c
#define HW4 4096
#define CN 1152

// ---------------- scratch ----------------
__device__ __nv_bfloat16  d_t1hi[4 * 128 * 256];            // [row=(b,c)][d] bf16 hi
__device__ __nv_bfloat16  d_t1lo[4 * 128 * 256];            // bf16 lo
__device__ __nv_bfloat16  d_w2hi[2304 * 256];               // [j][d] bf16 hi
__device__ __nv_bfloat16  d_w2lo[2304 * 256];               // bf16 lo
__device__ __nv_bfloat16  d_Ahi[4 * 256 * CN];              // [b][o][k=n*128+c] bf16 hi
__device__ __nv_bfloat16  d_Alo[4 * 256 * CN];              // bf16 lo
__device__ float          d_bm[4 * 256];                    // [b][o]
__device__ int            d_idx[4 * 9 * HW4 * 4];           // [b][n][hw][4] masked idx (unpadded)
__device__ float          d_gw [4 * 9 * HW4 * 4];           // [b][n][hw][4] masked weights

// ---------------- helpers ----------------
__device__ __forceinline__ uint32_t smem_u32(const void* p) {
    uint32_t a;
    asm("{ .reg .u64 t; cvta.to.shared.u64 t, %1; cvt.u32.u64 %0, t; }" : "=r"(a) : "l"(p));
    return a;
}
#define CP_ASYNC16(dst, src) asm volatile("cp.async.cg.shared.global [%0], [%1], 16;" :: "r"(dst), "l"(src))
#define CP_COMMIT()          asm volatile("cp.async.commit_group;" ::: "memory")
#define CP_WAIT(n)           asm volatile("cp.async.wait_group %0;" :: "n"(n) : "memory")
#define LDSM_X4(R0,R1,R2,R3,ADDR) \
    asm volatile("ldmatrix.sync.aligned.m8n8.x4.shared.b16 {%0,%1,%2,%3}, [%4];" \
                 : "=r"(R0),"=r"(R1),"=r"(R2),"=r"(R3) : "r"(ADDR))
#define LDSM_X2(R0,R1,ADDR) \
    asm volatile("ldmatrix.sync.aligned.m8n8.x2.shared.b16 {%0,%1}, [%2];" \
                 : "=r"(R0),"=r"(R1) : "r"(ADDR))
#define STS64V(A, R0, R1) \
    asm volatile("st.shared.v2.b32 [%0], {%1,%2};" :: "r"(A), "r"(R0), "r"(R1) : "memory")

__device__ __forceinline__ void mma_bf16(float* c, const uint32_t* a, const uint32_t* b) {
    asm volatile(
        "mma.sync.aligned.m16n8k16.row.col.f32.bf16.bf16.f32 "
        "{%0,%1,%2,%3}, {%4,%5,%6,%7}, {%8,%9}, {%0,%1,%2,%3};"
        : "+f"(c[0]), "+f"(c[1]), "+f"(c[2]), "+f"(c[3])
        : "r"(a[0]), "r"(a[1]), "r"(a[2]), "r"(a[3]), "r"(b[0]), "r"(b[1]));
}

__device__ __forceinline__ void split_bf16(float v, __nv_bfloat16& hi, __nv_bfloat16& lo) {
    hi = __float2bfloat16(v);
    lo = __float2bfloat16(v - __bfloat162float(hi));
}
__device__ __forceinline__ uint32_t pack2(__nv_bfloat16 a, __nv_bfloat16 b) {
    return (uint32_t)__bfloat16_as_ushort(a) | ((uint32_t)__bfloat16_as_ushort(b) << 16);
}

// ---------------- 1. fused prep: w1 (blocks 0..1023, 4 rows/warp) | w2split+bias (1024..3455) | offset (3456..3519)
__global__ void k_prep(const float* __restrict__ meta, const float* __restrict__ w1w,
                       const float* __restrict__ w1b, const float* __restrict__ w2w,
                       const float* __restrict__ blw, const float* __restrict__ blb,
                       const float* __restrict__ mio, const float* __restrict__ pw,
                       const float* __restrict__ pb) {
    __shared__ float4 sm4[256];
    __shared__ float sw[162];
    __shared__ float sb[18];
    int bid = blockIdx.x;
    if (bid < 1024) {
        // ---- hyper stage 1: 4 rows per warp, 8 float4 loads in flight ----
        if (threadIdx.x < 256) sm4[threadIdx.x] = ((const float4*)meta)[threadIdx.x];
        __syncthreads();
        int warp = (bid * 256 + threadIdx.x) >> 5;   // 0..8191
        int gw0 = warp * 4;
        int lane = threadIdx.x & 31;
        float4 wv[4][2];
        #pragma unroll
        for (int r = 0; r < 4; r++) {
            const float4* row = (const float4*)(w1w + (size_t)(gw0 + r) * 256);
            wv[r][0] = row[lane];
            wv[r][1] = row[lane + 32];
        }
        float acc[4][4];                              // [row][batch]
        #pragma unroll
        for (int bb = 0; bb < 4; bb++) {
            float4 m0 = sm4[bb * 64 + lane], m1 = sm4[bb * 64 + lane + 32];
            #pragma unroll
            for (int r = 0; r < 4; r++) {
                acc[r][bb] = wv[r][0].x * m0.x + wv[r][0].y * m0.y
                           + wv[r][0].z * m0.z + wv[r][0].w * m0.w
                           + wv[r][1].x * m1.x + wv[r][1].y * m1.y
                           + wv[r][1].z * m1.z + wv[r][1].w * m1.w;
            }
        }
        #pragma unroll
        for (int s = 16; s > 0; s >>= 1)
            #pragma unroll
            for (int r = 0; r < 4; r++)
                #pragma unroll
                for (int bb = 0; bb < 4; bb++)
                    acc[r][bb] += __shfl_xor_sync(~0u, acc[r][bb], s);
        if (lane < 4) {                               // lane r handles row gw0+r
            int r = lane;
            int gw = gw0 + r;
            float bbias = w1b[gw];
            #pragma unroll
            for (int bb = 0; bb < 4; bb++) {
                __nv_bfloat16 hi, lo;
                split_bf16(acc[r][bb] + bbias, hi, lo);
                d_t1hi[bb * 32768 + gw] = hi;
                d_t1lo[bb * 32768 + gw] = lo;
            }
        }
    } else if (bid < 3456) {
        int sub = bid - 1024;
        if (sub < 2304) {
            int i = sub * 256 + threadIdx.x;
            __nv_bfloat16 hi, lo;
            split_bf16(w2w[i], hi, lo);
            d_w2hi[i] = hi;
            d_w2lo[i] = lo;
        } else {
            int gw = ((sub - 2304) * 256 + threadIdx.x) >> 5;  // 0..1023
            int lane = threadIdx.x & 31;
            int b = gw >> 8, o = gw & 255;
            const float* row = blw + o * 256;
            const float* m = meta + b * 256;
            float a = 0.f;
            #pragma unroll
            for (int k = lane; k < 256; k += 32) a += row[k] * m[k];
            #pragma unroll
            for (int s = 16; s > 0; s >>= 1) a += __shfl_xor_sync(~0u, a, s);
            if (lane == 0) d_bm[gw] = a + blb[o];
        }
    } else {
        // ---- offset conv + masked sampling indices/weights ----
        int sub = bid - 3456;                 // 0..63
        int b = sub >> 4;
        int hw = (sub & 15) * 256 + threadIdx.x;
        if (threadIdx.x < 162) sw[threadIdx.x] = pw[threadIdx.x];
        if (threadIdx.x < 18)  sb[threadIdx.x] = pb[threadIdx.x];
        __syncthreads();
        int h = hw >> 6, w = hw & 63;
        const float* plane = mio + b * 4096;
        float v[9];
        #pragma unroll
        for (int kh = 0; kh < 3; kh++)
            #pragma unroll
            for (int kw = 0; kw < 3; kw++) {
                int hi = h - 1 + kh, wi = w - 1 + kw;
                v[kh * 3 + kw] = (hi >= 0 && hi < 64 && wi >= 0 && wi < 64) ? plane[hi * 64 + wi] : 0.f;
            }
        #pragma unroll
        for (int n = 0; n < 9; n++) {
            float offx = sb[n], offy = sb[9 + n];
            #pragma unroll
            for (int t = 0; t < 9; t++) {
                offx += v[t] * sw[n * 9 + t];
                offy += v[t] * sw[(9 + n) * 9 + t];
            }
            float px = (float)(h + 1) + (float)(n / 3 - 1) + offx;
            float py = (float)(w + 1) + (float)(n % 3 - 1) + offy;
            float fx = floorf(px), fy = floorf(py);
            int xlt = min(max((int)fx, 0), 65);
            int xrb = min(max((int)fx + 1, 0), 65);
            int ylt = min(max((int)fy, 0), 65);
            int yrb = min(max((int)fy + 1, 0), 65);
            float pcx = fminf(fmaxf(px, 0.f), 65.f);
            float pcy = fminf(fmaxf(py, 0.f), 65.f);
            float glt = (1.f + ((float)xlt - pcx)) * (1.f + ((float)ylt - pcy));
            float grb = (1.f - ((float)xrb - pcx)) * (1.f - ((float)yrb - pcy));
            float glb = (1.f + ((float)xlt - pcx)) * (1.f - ((float)yrb - pcy));
            float grt = (1.f - ((float)xrb - pcx)) * (1.f + ((float)ylt - pcy));
            int4 id;
            float4 g;
            #define MASK(X, Y, G, IDX, GO) { \
                bool vv = ((X) >= 1) && ((X) <= 64) && ((Y) >= 1) && ((Y) <= 64); \
                IDX = vv ? (((X) - 1) * 64 + ((Y) - 1)) : 0; \
                GO = vv ? (G) : 0.f; }
            MASK(xlt, ylt, glt, id.x, g.x);
            MASK(xrb, yrb, grb, id.y, g.y);
            MASK(xlt, yrb, glb, id.z, g.z);
            MASK(xrb, ylt, grt, id.w, g.w);
            #undef MASK
            int base = ((b * 9 + n) * HW4 + hw) * 4;
            *(int4*)(d_idx + base) = id;
            *(float4*)(d_gw + base) = g;
        }
    }
}

// ---------------- 2. hyper stage 2: bf16x3 mma GEMM 512x2304x256 -> A hi/lo (k=n*128+c) ----
#define H2P 80
#define H2A (128 * H2P)                    // 10240 per A component
#define H2B (64 * H2P)                     // 5120 per B component
#define H2STG (2 * H2A + 2 * H2B)          // 30720
#define H2SMEM (2 * H2STG)                 // 61440
__global__ __launch_bounds__(256, 1) void k_hyper2(const float* __restrict__ w2b) {
    extern __shared__ char smb[];
    uint32_t s0 = smem_u32(smb);
    int tid = threadIdx.x, wid = tid >> 5, lane = tid & 31;
    int row0 = blockIdx.y * 128;
    int col0 = blockIdx.x * 64;

    auto load_stage = [&](int stage, int k0) {
        uint32_t sa = s0 + stage * H2STG;
        #pragma unroll
        for (int i = 0; i < 2; i++) {
            int l = tid + i * 256;
            int r = l >> 2, seg = l & 3;
            CP_ASYNC16(sa + r * H2P + seg * 16,
                       d_t1hi + (size_t)(row0 + r) * 256 + k0 + seg * 8);
        }
        #pragma unroll
        for (int i = 0; i < 2; i++) {
            int l = tid + i * 256;
            int r = l >> 2, seg = l & 3;
            CP_ASYNC16(sa + H2A + r * H2P + seg * 16,
                       d_t1lo + (size_t)(row0 + r) * 256 + k0 + seg * 8);
        }
        {
            int r = tid >> 2, seg = tid & 3;
            CP_ASYNC16(sa + 2 * H2A + r * H2P + seg * 16,
                       d_w2hi + (size_t)(col0 + r) * 256 + k0 + seg * 8);
            CP_ASYNC16(sa + 2 * H2A + H2B + r * H2P + seg * 16,
                       d_w2lo + (size_t)(col0 + r) * 256 + k0 + seg * 8);
        }
    };

    float acc[4][2][4];
    #pragma unroll
    for (int i = 0; i < 4; i++)
        #pragma unroll
        for (int j = 0; j < 2; j++)
            #pragma unroll
            for (int q = 0; q < 4; q++) acc[i][j][q] = 0.f;

    load_stage(0, 0);
    CP_COMMIT();

    int mwarp = (wid & 1) * 64;
    int nwarp = (wid >> 1) * 16;
    int grp = lane >> 2, tig = lane & 3;
    uint32_t aRow = (uint32_t)(mwarp + (lane & 15)) * H2P + (((uint32_t)lane >> 4) << 4);
    int lB = lane & 15;
    uint32_t bRow = (uint32_t)(nwarp + (lB & 7)) * H2P + ((((uint32_t)lB >> 3) & 1) << 4);

    for (int it = 0; it < 8; it++) {
        int cur = it & 1;
        if (it + 1 < 8) {
            load_stage(1 - cur, (it + 1) * 32);
            CP_COMMIT();
            CP_WAIT(1);
        } else {
            CP_WAIT(0);
        }
        __syncthreads();
        uint32_t base = s0 + cur * H2STG;
        #pragma unroll
        for (int s = 0; s < 2; s++) {
            uint32_t kof = (uint32_t)s * 32;
            uint32_t bh[2][2], bl[2][2];
            #pragma unroll
            for (int nt = 0; nt < 2; nt++) {
                uint32_t ab = base + 2 * H2A + bRow + nt * (8 * H2P) + kof;
                LDSM_X2(bh[nt][0], bh[nt][1], ab);
                LDSM_X2(bl[nt][0], bl[nt][1], ab + H2B);
            }
            #pragma unroll
            for (int mt = 0; mt < 4; mt++) {
                uint32_t aa = base + aRow + mt * (16 * H2P) + kof;
                uint32_t ah[4], al[4];
                LDSM_X4(ah[0], ah[1], ah[2], ah[3], aa);
                LDSM_X4(al[0], al[1], al[2], al[3], aa + H2A);
                #pragma unroll
                for (int nt = 0; nt < 2; nt++) {
                    mma_bf16(acc[mt][nt], ah, bh[nt]);
                    mma_bf16(acc[mt][nt], ah, bl[nt]);
                    mma_bf16(acc[mt][nt], al, bh[nt]);
                }
            }
        }
        __syncthreads();
    }

    // epilogue: stage tile in smem, coalesced hi/lo store (k = n*128 + c)
    __syncthreads();
    float* Cs = (float*)smb;               // [128][68]
    #pragma unroll
    for (int mt = 0; mt < 4; mt++)
        #pragma unroll
        for (int nt = 0; nt < 2; nt++)
            #pragma unroll
            for (int q = 0; q < 4; q++) {
                int rloc = mwarp + mt * 16 + grp + ((q >> 1) ? 8 : 0);
                int cloc = nwarp + nt * 8 + tig * 2 + (q & 1);
                Cs[rloc * 68 + cloc] = acc[mt][nt][q];
            }
    __syncthreads();
    {
        int j = tid >> 2, q4 = tid & 3;
        int jj = col0 + j;
        int o = jj / 9, n = jj - o * 9;
        int bb = row0 >> 7;
        float wbv = w2b[jj];
        size_t dstoff = ((size_t)(bb * 256 + o)) * CN + n * 128 + q4 * 32;
        #pragma unroll
        for (int cl = 0; cl < 32; cl += 2) {
            float v0 = Cs[(q4 * 32 + cl) * 68 + j] + wbv;
            float v1 = Cs[(q4 * 32 + cl + 1) * 68 + j] + wbv;
            __nv_bfloat16 h0, l0, h1, l1;
            split_bf16(v0, h0, l0);
            split_bf16(v1, h1, l1);
            *(uint32_t*)(d_Ahi + dstoff + cl) = pack2(h0, h1);
            *(uint32_t*)(d_Alo + dstoff + cl) = pack2(l0, l1);
        }
    }
}

// ---------------- 3. fused gather + bf16x3 GEMM + LSTM gates (pipelined gather, 1 sync/iter) ----
#define KC 32
#define APITCH 40
#define AHB (256 * APITCH * 2)             // 20480
#define BHB (128 * APITCH * 2)             // 10240
#define OFF_AL AHB
#define OFF_BH (2 * AHB)
#define OFF_BL (2 * AHB + BHB)
#define STG (2 * AHB + 2 * BHB)            // 61440
#define NSTAGE 3
#define IDXOFF (NSTAGE * STG)              // 184320
#define GWOFF  (IDXOFF + 18432)
#define GSMEM  (GWOFF + 18432)             // 221184

__global__ __launch_bounds__(512, 1) void k_gemm_mma(const float* __restrict__ inp,
                                                     const float* __restrict__ hcur,
                                                     const float* __restrict__ ccur,
                                                     float* __restrict__ out) {
    extern __shared__ char smb[];
    uint32_t s0 = smem_u32(smb);
    int tid = threadIdx.x, wid = tid >> 5, lane = tid & 31;
    int b = blockIdx.y;
    int hw0 = blockIdx.x * 128;

    const __nv_bfloat16* Ahi = d_Ahi + (size_t)b * 256 * CN;
    const __nv_bfloat16* Alo = d_Alo + (size_t)b * 256 * CN;
    const float* ibase = inp + (size_t)b * 64 * 4096;
    const float* hbase = hcur + (size_t)b * 64 * 4096;

    auto loadA = [&](int stage, int k0) {
        uint32_t sa = s0 + stage * STG;
        #pragma unroll
        for (int i = 0; i < 2; i++) {
            int l = tid + i * 512;
            int r = l >> 2, seg = l & 3;
            CP_ASYNC16(sa + r * 80 + seg * 16, Ahi + (size_t)r * CN + k0 + seg * 8);
        }
        #pragma unroll
        for (int i = 0; i < 2; i++) {
            int l = tid + i * 512;
            int r = l >> 2, seg = l & 3;
            CP_ASYNC16(sa + OFF_AL + r * 80 + seg * 16, Alo + (size_t)r * CN + k0 + seg * 8);
        }
    };

    int hwl = tid >> 2;
    int cg = (tid & 3) << 3;

    auto issue_half = [&](int ch, int hf, float* L) {
        int n = ch >> 2, c0 = (ch & 3) << 5;
        int c = c0 + cg + hf * 4;
        int4 id = ((const int4*)(smb + IDXOFF))[n * 128 + hwl];
        const float* pl0 = (c < 64) ? (ibase + (size_t)c * 4096)
                                    : (hbase + (size_t)(c - 64) * 4096);
        #pragma unroll
        for (int j = 0; j < 4; j++) {
            const float* pl = pl0 + (size_t)j * 4096;
            L[j * 4 + 0] = pl[id.x];
            L[j * 4 + 1] = pl[id.y];
            L[j * 4 + 2] = pl[id.z];
            L[j * 4 + 3] = pl[id.w];
        }
    };
    auto store_half = [&](int stage, int ch, int hf, const float* L) {
        int n = ch >> 2;
        float4 g = ((const float4*)(smb + GWOFF))[n * 128 + hwl];
        float v[4];
        #pragma unroll
        for (int j = 0; j < 4; j++)
            v[j] = g.x * L[j * 4] + g.y * L[j * 4 + 1] + g.z * L[j * 4 + 2] + g.w * L[j * 4 + 3];
        __nv_bfloat16 h0, l0, h1, l1, h2, l2, h3, l3;
        split_bf16(v[0], h0, l0); split_bf16(v[1], h1, l1);
        split_bf16(v[2], h2, l2); split_bf16(v[3], h3, l3);
        uint32_t ba = s0 + stage * STG + OFF_BH + hwl * 80 + (cg + hf * 4) * 2;
        STS64V(ba, pack2(h0, h1), pack2(h2, h3));
        STS64V(ba + BHB, pack2(l0, l1), pack2(l2, l3));
    };

    for (int i = tid; i < 1152; i += 512) {
        int n = i >> 7, hh = i & 127;
        int gb = ((b * 9 + n) * HW4 + hw0 + hh) * 4;
        ((int4*)(smb + IDXOFF))[i] = *(const int4*)(d_idx + gb);
        ((float4*)(smb + GWOFF))[i] = *(const float4*)(d_gw + gb);
    }
    loadA(0, 0); CP_COMMIT();
    loadA(1, KC); CP_COMMIT();
    __syncthreads();
    {
        float L[16];
        issue_half(0, 0, L); store_half(0, 0, 0, L);
        issue_half(0, 1, L); store_half(0, 0, 1, L);
        issue_half(1, 0, L); store_half(1, 1, 0, L);
        issue_half(1, 1, L); store_half(1, 1, 1, L);
    }

    float acc[4][4][4];
    #pragma unroll
    for (int i = 0; i < 4; i++)
        #pragma unroll
        for (int j = 0; j < 4; j++)
            #pragma unroll
            for (int q = 0; q < 4; q++) acc[i][j][q] = 0.f;

    int mwarp = (wid & 3) * 64;
    int nwarp = (wid >> 2) * 32;
    int grp = lane >> 2, tig = lane & 3;
    uint32_t aRow = (uint32_t)(mwarp + (lane & 15)) * 80 + (((uint32_t)lane >> 4) << 4);
    uint32_t bRow4 = (uint32_t)((lane & 7) + ((lane & 16) >> 1)) * 80 + ((lane & 8) << 1);

    for (int it = 0; it < 36; it++) {
        int cur = it % NSTAGE;
        int pch = it + 2;
        bool hasP = pch < 36;
        int pst = pch % NSTAGE;
        if (it + 1 < 36) { CP_WAIT(1); } else { CP_WAIT(0); }
        __syncthreads();                  // single barrier per iteration
        float L[16];
        if (hasP) {
            loadA(pst, pch * KC);
            CP_COMMIT();
            issue_half(pch, 0, L);
        }
        uint32_t base = s0 + cur * STG;
        // ---- MMA s = 0 ----
        {
            uint32_t kof = 0;
            uint32_t bh[4][2], bl[4][2];
            #pragma unroll
            for (int p = 0; p < 2; p++) {
                uint32_t ab = base + OFF_BH + (uint32_t)(nwarp + p * 16) * 80 + bRow4 + kof;
                LDSM_X4(bh[2 * p][0], bh[2 * p][1], bh[2 * p + 1][0], bh[2 * p + 1][1], ab);
                LDSM_X4(bl[2 * p][0], bl[2 * p][1], bl[2 * p + 1][0], bl[2 * p + 1][1], ab + BHB);
            }
            #pragma unroll
            for (int mt = 0; mt < 4; mt++) {
                uint32_t aa = base + aRow + mt * (16 * 80) + kof;
                uint32_t ah[4], al[4];
                LDSM_X4(ah[0], ah[1], ah[2], ah[3], aa);
                LDSM_X4(al[0], al[1], al[2], al[3], aa + AHB);
                #pragma unroll
                for (int nt = 0; nt < 4; nt++) {
                    mma_bf16(acc[mt][nt], ah, bh[nt]);
                    mma_bf16(acc[mt][nt], ah, bl[nt]);
                    mma_bf16(acc[mt][nt], al, bh[nt]);
                }
            }
        }
        if (hasP) {
            store_half(pst, pch, 0, L);
            issue_half(pch, 1, L);
        }
        // ---- MMA s = 1 ----
        {
            uint32_t kof = 32;
            uint32_t bh[4][2], bl[4][2];
            #pragma unroll
            for (int p = 0; p < 2; p++) {
                uint32_t ab = base + OFF_BH + (uint32_t)(nwarp + p * 16) * 80 + bRow4 + kof;
                LDSM_X4(bh[2 * p][0], bh[2 * p][1], bh[2 * p + 1][0], bh[2 * p + 1][1], ab);
                LDSM_X4(bl[2 * p][0], bl[2 * p][1], bl[2 * p + 1][0], bl[2 * p + 1][1], ab + BHB);
            }
            #pragma unroll
            for (int mt = 0; mt < 4; mt++) {
                uint32_t aa = base + aRow + mt * (16 * 80) + kof;
                uint32_t ah[4], al[4];
                LDSM_X4(ah[0], ah[1], ah[2], ah[3], aa);
                LDSM_X4(al[0], al[1], al[2], al[3], aa + AHB);
                #pragma unroll
                for (int nt = 0; nt < 4; nt++) {
                    mma_bf16(acc[mt][nt], ah, bh[nt]);
                    mma_bf16(acc[mt][nt], ah, bl[nt]);
                    mma_bf16(acc[mt][nt], al, bh[nt]);
                }
            }
        }
        if (hasP) store_half(pst, pch, 1, L);
    }
    __syncthreads();                      // protect stage smem before epilogue reuse

    // ---- stage C tile (with bias) into smem, then fused LSTM gates ----
    float* Cs = (float*)smb;               // [256][132]
    const float* bmp = d_bm + b * 256;
    #pragma unroll
    for (int mt = 0; mt < 4; mt++) {
        int row = mwarp + mt * 16 + grp;
        float bz0 = bmp[row], bz1 = bmp[row + 8];
        #pragma unroll
        for (int nt = 0; nt < 4; nt++) {
            int col = nwarp + nt * 8 + tig * 2;
            Cs[row * 132 + col]           = acc[mt][nt][0] + bz0;
            Cs[row * 132 + col + 1]       = acc[mt][nt][1] + bz0;
            Cs[(row + 8) * 132 + col]     = acc[mt][nt][2] + bz1;
            Cs[(row + 8) * 132 + col + 1] = acc[mt][nt][3] + bz1;
        }
    }
    __syncthreads();
    #pragma unroll
    for (int q = 0; q < 16; q++) {
        int lin = q * 512 + tid;           // < 8192
        int hid = lin >> 7, hw = lin & 127;
        float ci = Cs[hid * 132 + hw];
        float cf = Cs[(hid + 64) * 132 + hw];
        float co = Cs[(hid + 128) * 132 + hw];
        float cg2 = Cs[(hid + 192) * 132 + hw];
        float ig = 1.f / (1.f + expf(-ci));
        float fg = 1.f / (1.f + expf(-cf));
        float og = 1.f / (1.f + expf(-co));
        float gg = tanhf(cg2);
        int g = (b * 64 + hid) * HW4 + hw0 + hw;
        float cn = fg * ccur[g] + ig * gg;
        float hn = og * tanhf(cn);
        out[g] = hn;
        out[1048576 + g] = cn;
    }
}

// ---------------- launch ----------------
extern "C" void kernel_launch(void* const* d_in, const int* in_sizes, int n_in,
                              void* d_out, int out_size) {
    const float* inp  = (const float*)d_in[0];
    const float* hcur = (const float*)d_in[1];
    const float* ccur = (const float*)d_in[2];
    const float* meta = (const float*)d_in[3];
    const float* mio  = (const float*)d_in[4];
    const float* w1w  = (const float*)d_in[5];
    const float* w1b  = (const float*)d_in[6];
    const float* w2w  = (const float*)d_in[7];
    const float* w2b  = (const float*)d_in[8];
    const float* blw  = (const float*)d_in[9];
    const float* blb  = (const float*)d_in[10];
    const float* pw   = (const float*)d_in[11];
    const float* pb   = (const float*)d_in[12];
    float* out = (float*)d_out;

    cudaFuncSetAttribute(k_hyper2, cudaFuncAttributeMaxDynamicSharedMemorySize, H2SMEM);
    cudaFuncSetAttribute(k_gemm_mma, cudaFuncAttributeMaxDynamicSharedMemorySize, GSMEM);

    k_prep    <<<3520, 256>>>(meta, w1w, w1b, w2w, blw, blb, mio, pw, pb);
    k_hyper2  <<<dim3(36, 4), 256, H2SMEM>>>(w2b);
    k_gemm_mma<<<dim3(32, 4), 512, GSMEM>>>(inp, hcur, ccur, out);
}

// round 14
// speedup vs baseline: 1.1068x; 1.1068x over previous
#include <cuda_runtime.h>
#include <cuda_bf16.h>
#include <math.h>
#include <stdint.h>

// B=4, CIN=64, HID=64, H=W=64, K=3, N=9, D=256, INC=128, OUTC=256
// HW=4096, CN = INC*9 = 1152 ; k-order: k = n*128 + c
#define HW4 4096
#define CN 1152

// ---------------- scratch ----------------
__device__ __nv_bfloat16  d_t1hi[4 * 128 * 256];            // [row=(b,c)][d] bf16 hi
__device__ __nv_bfloat16  d_t1lo[4 * 128 * 256];            // bf16 lo
__device__ __nv_bfloat16  d_w2hi[2304 * 256];               // [j][d] bf16 hi
__device__ __nv_bfloat16  d_w2lo[2304 * 256];               // bf16 lo
__device__ __nv_bfloat16  d_Ahi[4 * 256 * CN];              // [b][o][k=n*128+c] bf16 hi
__device__ __nv_bfloat16  d_Alo[4 * 256 * CN];              // bf16 lo
__device__ float          d_bm[4 * 256];                    // [b][o]
__device__ int            d_idx[4 * 9 * HW4 * 4];           // [b][n][hw][4] masked idx (unpadded)
__device__ float          d_gw [4 * 9 * HW4 * 4];           // [b][n][hw][4] masked weights

// ---------------- helpers ----------------
__device__ __forceinline__ uint32_t smem_u32(const void* p) {
    uint32_t a;
    asm("{ .reg .u64 t; cvta.to.shared.u64 t, %1; cvt.u32.u64 %0, t; }" : "=r"(a) : "l"(p));
    return a;
}
#define CP_ASYNC16(dst, src) asm volatile("cp.async.cg.shared.global [%0], [%1], 16;" :: "r"(dst), "l"(src))
#define CP_COMMIT()          asm volatile("cp.async.commit_group;" ::: "memory")
#define CP_WAIT(n)           asm volatile("cp.async.wait_group %0;" :: "n"(n) : "memory")
#define LDSM_X4(R0,R1,R2,R3,ADDR) \
    asm volatile("ldmatrix.sync.aligned.m8n8.x4.shared.b16 {%0,%1,%2,%3}, [%4];" \
                 : "=r"(R0),"=r"(R1),"=r"(R2),"=r"(R3) : "r"(ADDR))
#define LDSM_X2(R0,R1,ADDR) \
    asm volatile("ldmatrix.sync.aligned.m8n8.x2.shared.b16 {%0,%1}, [%2];" \
                 : "=r"(R0),"=r"(R1) : "r"(ADDR))
#define STS64V(A, R0, R1) \
    asm volatile("st.shared.v2.b32 [%0], {%1,%2};" :: "r"(A), "r"(R0), "r"(R1) : "memory")

__device__ __forceinline__ void mma_bf16(float* c, const uint32_t* a, const uint32_t* b) {
    asm volatile(
        "mma.sync.aligned.m16n8k16.row.col.f32.bf16.bf16.f32 "
        "{%0,%1,%2,%3}, {%4,%5,%6,%7}, {%8,%9}, {%0,%1,%2,%3};"
        : "+f"(c[0]), "+f"(c[1]), "+f"(c[2]), "+f"(c[3])
        : "r"(a[0]), "r"(a[1]), "r"(a[2]), "r"(a[3]), "r"(b[0]), "r"(b[1]));
}

__device__ __forceinline__ void split_bf16(float v, __nv_bfloat16& hi, __nv_bfloat16& lo) {
    hi = __float2bfloat16(v);
    lo = __float2bfloat16(v - __bfloat162float(hi));
}
__device__ __forceinline__ uint32_t pack2(__nv_bfloat16 a, __nv_bfloat16 b) {
    return (uint32_t)__bfloat16_as_ushort(a) | ((uint32_t)__bfloat16_as_ushort(b) << 16);
}

// ---------------- 1. fused prep ----------------
// blocks: w1 [0,1024) 4 rows/warp | w2split [1024,1600) float4 | bias [1600,1728) | offset [1728,1792)
__global__ void k_prep(const float* __restrict__ meta, const float* __restrict__ w1w,
                       const float* __restrict__ w1b, const float* __restrict__ w2w,
                       const float* __restrict__ blw, const float* __restrict__ blb,
                       const float* __restrict__ mio, const float* __restrict__ pw,
                       const float* __restrict__ pb) {
    __shared__ float4 sm4[256];
    __shared__ float sw[162];
    __shared__ float sb[18];
    int bid = blockIdx.x;
    if (bid < 1024) {
        // ---- hyper stage 1: 4 rows per warp, 8 float4 loads in flight ----
        if (threadIdx.x < 256) sm4[threadIdx.x] = ((const float4*)meta)[threadIdx.x];
        __syncthreads();
        int warp = (bid * 256 + threadIdx.x) >> 5;   // 0..8191
        int gw0 = warp * 4;
        int lane = threadIdx.x & 31;
        float4 wv[4][2];
        #pragma unroll
        for (int r = 0; r < 4; r++) {
            const float4* row = (const float4*)(w1w + (size_t)(gw0 + r) * 256);
            wv[r][0] = row[lane];
            wv[r][1] = row[lane + 32];
        }
        float acc[4][4];                              // [row][batch]
        #pragma unroll
        for (int bb = 0; bb < 4; bb++) {
            float4 m0 = sm4[bb * 64 + lane], m1 = sm4[bb * 64 + lane + 32];
            #pragma unroll
            for (int r = 0; r < 4; r++) {
                acc[r][bb] = wv[r][0].x * m0.x + wv[r][0].y * m0.y
                           + wv[r][0].z * m0.z + wv[r][0].w * m0.w
                           + wv[r][1].x * m1.x + wv[r][1].y * m1.y
                           + wv[r][1].z * m1.z + wv[r][1].w * m1.w;
            }
        }
        #pragma unroll
        for (int s = 16; s > 0; s >>= 1)
            #pragma unroll
            for (int r = 0; r < 4; r++)
                #pragma unroll
                for (int bb = 0; bb < 4; bb++)
                    acc[r][bb] += __shfl_xor_sync(~0u, acc[r][bb], s);
        if (lane < 4) {
            int r = lane;
            int gw = gw0 + r;
            float bbias = w1b[gw];
            #pragma unroll
            for (int bb = 0; bb < 4; bb++) {
                __nv_bfloat16 hi, lo;
                split_bf16(acc[r][bb] + bbias, hi, lo);
                d_t1hi[bb * 32768 + gw] = hi;
                d_t1lo[bb * 32768 + gw] = lo;
            }
        }
    } else if (bid < 1600) {
        // ---- w2 split, vectorized: 576 blocks x 256 threads x 4 elems ----
        int idx = (bid - 1024) * 1024 + threadIdx.x * 4;
        float4 v = *(const float4*)(w2w + idx);
        __nv_bfloat16 h0, l0, h1, l1, h2, l2, h3, l3;
        split_bf16(v.x, h0, l0); split_bf16(v.y, h1, l1);
        split_bf16(v.z, h2, l2); split_bf16(v.w, h3, l3);
        uint2 hv = make_uint2(pack2(h0, h1), pack2(h2, h3));
        uint2 lv = make_uint2(pack2(l0, l1), pack2(l2, l3));
        *(uint2*)(d_w2hi + idx) = hv;
        *(uint2*)(d_w2lo + idx) = lv;
    } else if (bid < 1728) {
        int gw = ((bid - 1600) * 256 + threadIdx.x) >> 5;  // 0..1023
        int lane = threadIdx.x & 31;
        int b = gw >> 8, o = gw & 255;
        const float* row = blw + o * 256;
        const float* m = meta + b * 256;
        float a = 0.f;
        #pragma unroll
        for (int k = lane; k < 256; k += 32) a += row[k] * m[k];
        #pragma unroll
        for (int s = 16; s > 0; s >>= 1) a += __shfl_xor_sync(~0u, a, s);
        if (lane == 0) d_bm[gw] = a + blb[o];
    } else {
        // ---- offset conv + masked sampling indices/weights ----
        int sub = bid - 1728;                 // 0..63
        int b = sub >> 4;
        int hw = (sub & 15) * 256 + threadIdx.x;
        if (threadIdx.x < 162) sw[threadIdx.x] = pw[threadIdx.x];
        if (threadIdx.x < 18)  sb[threadIdx.x] = pb[threadIdx.x];
        __syncthreads();
        int h = hw >> 6, w = hw & 63;
        const float* plane = mio + b * 4096;
        float v[9];
        #pragma unroll
        for (int kh = 0; kh < 3; kh++)
            #pragma unroll
            for (int kw = 0; kw < 3; kw++) {
                int hi = h - 1 + kh, wi = w - 1 + kw;
                v[kh * 3 + kw] = (hi >= 0 && hi < 64 && wi >= 0 && wi < 64) ? plane[hi * 64 + wi] : 0.f;
            }
        #pragma unroll
        for (int n = 0; n < 9; n++) {
            float offx = sb[n], offy = sb[9 + n];
            #pragma unroll
            for (int t = 0; t < 9; t++) {
                offx += v[t] * sw[n * 9 + t];
                offy += v[t] * sw[(9 + n) * 9 + t];
            }
            float px = (float)(h + 1) + (float)(n / 3 - 1) + offx;
            float py = (float)(w + 1) + (float)(n % 3 - 1) + offy;
            float fx = floorf(px), fy = floorf(py);
            int xlt = min(max((int)fx, 0), 65);
            int xrb = min(max((int)fx + 1, 0), 65);
            int ylt = min(max((int)fy, 0), 65);
            int yrb = min(max((int)fy + 1, 0), 65);
            float pcx = fminf(fmaxf(px, 0.f), 65.f);
            float pcy = fminf(fmaxf(py, 0.f), 65.f);
            float glt = (1.f + ((float)xlt - pcx)) * (1.f + ((float)ylt - pcy));
            float grb = (1.f - ((float)xrb - pcx)) * (1.f - ((float)yrb - pcy));
            float glb = (1.f + ((float)xlt - pcx)) * (1.f - ((float)yrb - pcy));
            float grt = (1.f - ((float)xrb - pcx)) * (1.f + ((float)ylt - pcy));
            int4 id;
            float4 g;
            #define MASK(X, Y, G, IDX, GO) { \
                bool vv = ((X) >= 1) && ((X) <= 64) && ((Y) >= 1) && ((Y) <= 64); \
                IDX = vv ? (((X) - 1) * 64 + ((Y) - 1)) : 0; \
                GO = vv ? (G) : 0.f; }
            MASK(xlt, ylt, glt, id.x, g.x);
            MASK(xrb, yrb, grb, id.y, g.y);
            MASK(xlt, yrb, glb, id.z, g.z);
            MASK(xrb, ylt, grt, id.w, g.w);
            #undef MASK
            int base = ((b * 9 + n) * HW4 + hw) * 4;
            *(int4*)(d_idx + base) = id;
            *(float4*)(d_gw + base) = g;
        }
    }
}

// ---------------- 2. hyper stage 2: bf16x3 mma GEMM 512x2304x256 -> A hi/lo (k=n*128+c) ----
#define H2P 80
#define H2A (128 * H2P)                    // 10240 per A component
#define H2B (64 * H2P)                     // 5120 per B component
#define H2STG (2 * H2A + 2 * H2B)          // 30720
#define H2SMEM (2 * H2STG)                 // 61440
__global__ __launch_bounds__(256, 1) void k_hyper2(const float* __restrict__ w2b) {
    extern __shared__ char smb[];
    uint32_t s0 = smem_u32(smb);
    int tid = threadIdx.x, wid = tid >> 5, lane = tid & 31;
    int row0 = blockIdx.y * 128;
    int col0 = blockIdx.x * 64;

    auto load_stage = [&](int stage, int k0) {
        uint32_t sa = s0 + stage * H2STG;
        #pragma unroll
        for (int i = 0; i < 2; i++) {
            int l = tid + i * 256;
            int r = l >> 2, seg = l & 3;
            CP_ASYNC16(sa + r * H2P + seg * 16,
                       d_t1hi + (size_t)(row0 + r) * 256 + k0 + seg * 8);
        }
        #pragma unroll
        for (int i = 0; i < 2; i++) {
            int l = tid + i * 256;
            int r = l >> 2, seg = l & 3;
            CP_ASYNC16(sa + H2A + r * H2P + seg * 16,
                       d_t1lo + (size_t)(row0 + r) * 256 + k0 + seg * 8);
        }
        {
            int r = tid >> 2, seg = tid & 3;
            CP_ASYNC16(sa + 2 * H2A + r * H2P + seg * 16,
                       d_w2hi + (size_t)(col0 + r) * 256 + k0 + seg * 8);
            CP_ASYNC16(sa + 2 * H2A + H2B + r * H2P + seg * 16,
                       d_w2lo + (size_t)(col0 + r) * 256 + k0 + seg * 8);
        }
    };

    float acc[4][2][4];
    #pragma unroll
    for (int i = 0; i < 4; i++)
        #pragma unroll
        for (int j = 0; j < 2; j++)
            #pragma unroll
            for (int q = 0; q < 4; q++) acc[i][j][q] = 0.f;

    load_stage(0, 0);
    CP_COMMIT();

    int mwarp = (wid & 1) * 64;
    int nwarp = (wid >> 1) * 16;
    int grp = lane >> 2, tig = lane & 3;
    uint32_t aRow = (uint32_t)(mwarp + (lane & 15)) * H2P + (((uint32_t)lane >> 4) << 4);
    int lB = lane & 15;
    uint32_t bRow = (uint32_t)(nwarp + (lB & 7)) * H2P + ((((uint32_t)lB >> 3) & 1) << 4);

    for (int it = 0; it < 8; it++) {
        int cur = it & 1;
        if (it + 1 < 8) {
            load_stage(1 - cur, (it + 1) * 32);
            CP_COMMIT();
            CP_WAIT(1);
        } else {
            CP_WAIT(0);
        }
        __syncthreads();
        uint32_t base = s0 + cur * H2STG;
        #pragma unroll
        for (int s = 0; s < 2; s++) {
            uint32_t kof = (uint32_t)s * 32;
            uint32_t bh[2][2], bl[2][2];
            #pragma unroll
            for (int nt = 0; nt < 2; nt++) {
                uint32_t ab = base + 2 * H2A + bRow + nt * (8 * H2P) + kof;
                LDSM_X2(bh[nt][0], bh[nt][1], ab);
                LDSM_X2(bl[nt][0], bl[nt][1], ab + H2B);
            }
            #pragma unroll
            for (int mt = 0; mt < 4; mt++) {
                uint32_t aa = base + aRow + mt * (16 * H2P) + kof;
                uint32_t ah[4], al[4];
                LDSM_X4(ah[0], ah[1], ah[2], ah[3], aa);
                LDSM_X4(al[0], al[1], al[2], al[3], aa + H2A);
                #pragma unroll
                for (int nt = 0; nt < 2; nt++) {
                    mma_bf16(acc[mt][nt], ah, bh[nt]);
                    mma_bf16(acc[mt][nt], ah, bl[nt]);
                    mma_bf16(acc[mt][nt], al, bh[nt]);
                }
            }
        }
        __syncthreads();
    }

    // epilogue: stage tile in smem, coalesced hi/lo store (k = n*128 + c)
    __syncthreads();
    float* Cs = (float*)smb;               // [128][68]
    #pragma unroll
    for (int mt = 0; mt < 4; mt++)
        #pragma unroll
        for (int nt = 0; nt < 2; nt++)
            #pragma unroll
            for (int q = 0; q < 4; q++) {
                int rloc = mwarp + mt * 16 + grp + ((q >> 1) ? 8 : 0);
                int cloc = nwarp + nt * 8 + tig * 2 + (q & 1);
                Cs[rloc * 68 + cloc] = acc[mt][nt][q];
            }
    __syncthreads();
    {
        int j = tid >> 2, q4 = tid & 3;
        int jj = col0 + j;
        int o = jj / 9, n = jj - o * 9;
        int bb = row0 >> 7;
        float wbv = w2b[jj];
        size_t dstoff = ((size_t)(bb * 256 + o)) * CN + n * 128 + q4 * 32;
        #pragma unroll
        for (int cl = 0; cl < 32; cl += 2) {
            float v0 = Cs[(q4 * 32 + cl) * 68 + j] + wbv;
            float v1 = Cs[(q4 * 32 + cl + 1) * 68 + j] + wbv;
            __nv_bfloat16 h0, l0, h1, l1;
            split_bf16(v0, h0, l0);
            split_bf16(v1, h1, l1);
            *(uint32_t*)(d_Ahi + dstoff + cl) = pack2(h0, h1);
            *(uint32_t*)(d_Alo + dstoff + cl) = pack2(l0, l1);
        }
    }
}

// ---------------- 3. fused gather + bf16x3 GEMM + LSTM gates (hoisted gather issue) ----
#define KC 32
#define APITCH 40
#define AHB (256 * APITCH * 2)             // 20480
#define BHB (128 * APITCH * 2)             // 10240
#define OFF_AL AHB
#define OFF_BH (2 * AHB)
#define OFF_BL (2 * AHB + BHB)
#define STG (2 * AHB + 2 * BHB)            // 61440
#define NSTAGE 3
#define IDXOFF (NSTAGE * STG)              // 184320
#define GWOFF  (IDXOFF + 18432)
#define GSMEM  (GWOFF + 18432)             // 221184

__global__ __launch_bounds__(512, 1) void k_gemm_mma(const float* __restrict__ inp,
                                                     const float* __restrict__ hcur,
                                                     const float* __restrict__ ccur,
                                                     float* __restrict__ out) {
    extern __shared__ char smb[];
    uint32_t s0 = smem_u32(smb);
    int tid = threadIdx.x, wid = tid >> 5, lane = tid & 31;
    int b = blockIdx.y;
    int hw0 = blockIdx.x * 128;

    const __nv_bfloat16* Ahi = d_Ahi + (size_t)b * 256 * CN;
    const __nv_bfloat16* Alo = d_Alo + (size_t)b * 256 * CN;
    const float* ibase = inp + (size_t)b * 64 * 4096;
    const float* hbase = hcur + (size_t)b * 64 * 4096;

    auto loadA = [&](int stage, int k0) {
        uint32_t sa = s0 + stage * STG;
        #pragma unroll
        for (int i = 0; i < 2; i++) {
            int l = tid + i * 512;
            int r = l >> 2, seg = l & 3;
            CP_ASYNC16(sa + r * 80 + seg * 16, Ahi + (size_t)r * CN + k0 + seg * 8);
        }
        #pragma unroll
        for (int i = 0; i < 2; i++) {
            int l = tid + i * 512;
            int r = l >> 2, seg = l & 3;
            CP_ASYNC16(sa + OFF_AL + r * 80 + seg * 16, Alo + (size_t)r * CN + k0 + seg * 8);
        }
    };

    int hwl = tid >> 2;
    int cg = (tid & 3) << 3;

    auto issue_half = [&](int ch, int hf, float* L) {
        int n = ch >> 2, c0 = (ch & 3) << 5;
        int c = c0 + cg + hf * 4;
        int4 id = ((const int4*)(smb + IDXOFF))[n * 128 + hwl];
        const float* pl0 = (c < 64) ? (ibase + (size_t)c * 4096)
                                    : (hbase + (size_t)(c - 64) * 4096);
        #pragma unroll
        for (int j = 0; j < 4; j++) {
            const float* pl = pl0 + (size_t)j * 4096;
            L[j * 4 + 0] = pl[id.x];
            L[j * 4 + 1] = pl[id.y];
            L[j * 4 + 2] = pl[id.z];
            L[j * 4 + 3] = pl[id.w];
        }
    };
    auto store_half = [&](int stage, int ch, int hf, const float* L) {
        int n = ch >> 2;
        float4 g = ((const float4*)(smb + GWOFF))[n * 128 + hwl];
        float v[4];
        #pragma unroll
        for (int j = 0; j < 4; j++)
            v[j] = g.x * L[j * 4] + g.y * L[j * 4 + 1] + g.z * L[j * 4 + 2] + g.w * L[j * 4 + 3];
        __nv_bfloat16 h0, l0, h1, l1, h2, l2, h3, l3;
        split_bf16(v[0], h0, l0); split_bf16(v[1], h1, l1);
        split_bf16(v[2], h2, l2); split_bf16(v[3], h3, l3);
        uint32_t ba = s0 + stage * STG + OFF_BH + hwl * 80 + (cg + hf * 4) * 2;
        STS64V(ba, pack2(h0, h1), pack2(h2, h3));
        STS64V(ba + BHB, pack2(l0, l1), pack2(l2, l3));
    };

    for (int i = tid; i < 1152; i += 512) {
        int n = i >> 7, hh = i & 127;
        int gb = ((b * 9 + n) * HW4 + hw0 + hh) * 4;
        ((int4*)(smb + IDXOFF))[i] = *(const int4*)(d_idx + gb);
        ((float4*)(smb + GWOFF))[i] = *(const float4*)(d_gw + gb);
    }
    loadA(0, 0); CP_COMMIT();
    loadA(1, KC); CP_COMMIT();
    __syncthreads();
    {
        float L[16];
        issue_half(0, 0, L); store_half(0, 0, 0, L);
        issue_half(0, 1, L); store_half(0, 0, 1, L);
        issue_half(1, 0, L); store_half(1, 1, 0, L);
        issue_half(1, 1, L); store_half(1, 1, 1, L);
    }

    float acc[4][4][4];
    #pragma unroll
    for (int i = 0; i < 4; i++)
        #pragma unroll
        for (int j = 0; j < 4; j++)
            #pragma unroll
            for (int q = 0; q < 4; q++) acc[i][j][q] = 0.f;

    int mwarp = (wid & 3) * 64;
    int nwarp = (wid >> 2) * 32;
    int grp = lane >> 2, tig = lane & 3;
    uint32_t aRow = (uint32_t)(mwarp + (lane & 15)) * 80 + (((uint32_t)lane >> 4) << 4);
    uint32_t bRow4 = (uint32_t)((lane & 7) + ((lane & 16) >> 1)) * 80 + ((lane & 8) << 1);

    for (int it = 0; it < 36; it++) {
        int cur = it % NSTAGE;
        int pch = it + 2;
        bool hasP = pch < 36;
        int pst = pch % NSTAGE;
        float L[16];
        // gather LDGs are register-only: issue BEFORE the wait/barrier so their
        // latency overlaps the barrier + loadA issue + s0 MMA block.
        if (hasP) issue_half(pch, 0, L);
        if (it + 1 < 36) { CP_WAIT(1); } else { CP_WAIT(0); }
        __syncthreads();                  // single barrier per iteration
        if (hasP) {
            loadA(pst, pch * KC);
            CP_COMMIT();
        }
        uint32_t base = s0 + cur * STG;
        // ---- MMA s = 0 ----
        {
            uint32_t kof = 0;
            uint32_t bh[4][2], bl[4][2];
            #pragma unroll
            for (int p = 0; p < 2; p++) {
                uint32_t ab = base + OFF_BH + (uint32_t)(nwarp + p * 16) * 80 + bRow4 + kof;
                LDSM_X4(bh[2 * p][0], bh[2 * p][1], bh[2 * p + 1][0], bh[2 * p + 1][1], ab);
                LDSM_X4(bl[2 * p][0], bl[2 * p][1], bl[2 * p + 1][0], bl[2 * p + 1][1], ab + BHB);
            }
            #pragma unroll
            for (int mt = 0; mt < 4; mt++) {
                uint32_t aa = base + aRow + mt * (16 * 80) + kof;
                uint32_t ah[4], al[4];
                LDSM_X4(ah[0], ah[1], ah[2], ah[3], aa);
                LDSM_X4(al[0], al[1], al[2], al[3], aa + AHB);
                #pragma unroll
                for (int nt = 0; nt < 4; nt++) {
                    mma_bf16(acc[mt][nt], ah, bh[nt]);
                    mma_bf16(acc[mt][nt], ah, bl[nt]);
                    mma_bf16(acc[mt][nt], al, bh[nt]);
                }
            }
        }
        if (hasP) {
            store_half(pst, pch, 0, L);
            issue_half(pch, 1, L);
        }
        // ---- MMA s = 1 ----
        {
            uint32_t kof = 32;
            uint32_t bh[4][2], bl[4][2];
            #pragma unroll
            for (int p = 0; p < 2; p++) {
                uint32_t ab = base + OFF_BH + (uint32_t)(nwarp + p * 16) * 80 + bRow4 + kof;
                LDSM_X4(bh[2 * p][0], bh[2 * p][1], bh[2 * p + 1][0], bh[2 * p + 1][1], ab);
                LDSM_X4(bl[2 * p][0], bl[2 * p][1], bl[2 * p + 1][0], bl[2 * p + 1][1], ab + BHB);
            }
            #pragma unroll
            for (int mt = 0; mt < 4; mt++) {
                uint32_t aa = base + aRow + mt * (16 * 80) + kof;
                uint32_t ah[4], al[4];
                LDSM_X4(ah[0], ah[1], ah[2], ah[3], aa);
                LDSM_X4(al[0], al[1], al[2], al[3], aa + AHB);
                #pragma unroll
                for (int nt = 0; nt < 4; nt++) {
                    mma_bf16(acc[mt][nt], ah, bh[nt]);
                    mma_bf16(acc[mt][nt], ah, bl[nt]);
                    mma_bf16(acc[mt][nt], al, bh[nt]);
                }
            }
        }
        if (hasP) store_half(pst, pch, 1, L);
    }
    __syncthreads();                      // protect stage smem before epilogue reuse

    // ---- stage C tile (with bias) into smem, then fused LSTM gates ----
    float* Cs = (float*)smb;               // [256][132]
    const float* bmp = d_bm + b * 256;
    #pragma unroll
    for (int mt = 0; mt < 4; mt++) {
        int row = mwarp + mt * 16 + grp;
        float bz0 = bmp[row], bz1 = bmp[row + 8];
        #pragma unroll
        for (int nt = 0; nt < 4; nt++) {
            int col = nwarp + nt * 8 + tig * 2;
            Cs[row * 132 + col]           = acc[mt][nt][0] + bz0;
            Cs[row * 132 + col + 1]       = acc[mt][nt][1] + bz0;
            Cs[(row + 8) * 132 + col]     = acc[mt][nt][2] + bz1;
            Cs[(row + 8) * 132 + col + 1] = acc[mt][nt][3] + bz1;
        }
    }
    __syncthreads();
    #pragma unroll
    for (int q = 0; q < 16; q++) {
        int lin = q * 512 + tid;           // < 8192
        int hid = lin >> 7, hw = lin & 127;
        float ci = Cs[hid * 132 + hw];
        float cf = Cs[(hid + 64) * 132 + hw];
        float co = Cs[(hid + 128) * 132 + hw];
        float cg2 = Cs[(hid + 192) * 132 + hw];
        float ig = 1.f / (1.f + expf(-ci));
        float fg = 1.f / (1.f + expf(-cf));
        float og = 1.f / (1.f + expf(-co));
        float gg = tanhf(cg2);
        int g = (b * 64 + hid) * HW4 + hw0 + hw;
        float cn = fg * ccur[g] + ig * gg;
        float hn = og * tanhf(cn);
        out[g] = hn;
        out[1048576 + g] = cn;
    }
}

// ---------------- launch ----------------
extern "C" void kernel_launch(void* const* d_in, const int* in_sizes, int n_in,
                              void* d_out, int out_size) {
    const float* inp  = (const float*)d_in[0];
    const float* hcur = (const float*)d_in[1];
    const float* ccur = (const float*)d_in[2];
    const float* meta = (const float*)d_in[3];
    const float* mio  = (const float*)d_in[4];
    const float* w1w  = (const float*)d_in[5];
    const float* w1b  = (const float*)d_in[6];
    const float* w2w  = (const float*)d_in[7];
    const float* w2b  = (const float*)d_in[8];
    const float* blw  = (const float*)d_in[9];
    const float* blb  = (const float*)d_in[10];
    const float* pw   = (const float*)d_in[11];
    const float* pb   = (const float*)d_in[12];
    float* out = (float*)d_out;

    cudaFuncSetAttribute(k_hyper2, cudaFuncAttributeMaxDynamicSharedMemorySize, H2SMEM);
    cudaFuncSetAttribute(k_gemm_mma, cudaFuncAttributeMaxDynamicSharedMemorySize, GSMEM);

    k_prep    <<<1792, 256>>>(meta, w1w, w1b, w2w, blw, blb, mio, pw, pb);
    k_hyper2  <<<dim3(36, 4), 256, H2SMEM>>>(w2b);
    k_gemm_mma<<<dim3(32, 4), 512, GSMEM>>>(inp, hcur, ccur, out);
}

// round 15
// speedup vs baseline: 1.1073x; 1.0004x over previous
#include <cuda_runtime.h>
#include <cuda_bf16.h>
#include <math.h>
#include <stdint.h>

// B=4, CIN=64, HID=64, H=W=64, K=3, N=9, D=256, INC=128, OUTC=256
// HW=4096, CN = INC*9 = 1152 ; k-order: k = n*128 + c
#define HW4 4096
#define CN 1152

// ---------------- scratch ----------------
__device__ __nv_bfloat16  d_t1hi[4 * 128 * 256];            // [row=(b,c)][d] bf16 hi
__device__ __nv_bfloat16  d_t1lo[4 * 128 * 256];            // bf16 lo
__device__ __nv_bfloat16  d_w2hi[2304 * 256];               // [j][d] bf16 hi
__device__ __nv_bfloat16  d_w2lo[2304 * 256];               // bf16 lo
__device__ __nv_bfloat16  d_Ahi[4 * 256 * CN];              // [b][o][k=n*128+c] bf16 hi
__device__ __nv_bfloat16  d_Alo[4 * 256 * CN];              // bf16 lo
__device__ float          d_bm[4 * 256];                    // [b][o]
__device__ int            d_idx[4 * 9 * HW4 * 4];           // [b][n][hw][4] masked idx (unpadded)
__device__ float          d_gw [4 * 9 * HW4 * 4];           // [b][n][hw][4] masked weights

// ---------------- helpers ----------------
__device__ __forceinline__ uint32_t smem_u32(const void* p) {
    uint32_t a;
    asm("{ .reg .u64 t; cvta.to.shared.u64 t, %1; cvt.u32.u64 %0, t; }" : "=r"(a) : "l"(p));
    return a;
}
#define CP_ASYNC16(dst, src) asm volatile("cp.async.cg.shared.global [%0], [%1], 16;" :: "r"(dst), "l"(src))
#define CP_COMMIT()          asm volatile("cp.async.commit_group;" ::: "memory")
#define CP_WAIT(n)           asm volatile("cp.async.wait_group %0;" :: "n"(n) : "memory")
#define LDSM_X4(R0,R1,R2,R3,ADDR) \
    asm volatile("ldmatrix.sync.aligned.m8n8.x4.shared.b16 {%0,%1,%2,%3}, [%4];" \
                 : "=r"(R0),"=r"(R1),"=r"(R2),"=r"(R3) : "r"(ADDR))
#define LDSM_X2(R0,R1,ADDR) \
    asm volatile("ldmatrix.sync.aligned.m8n8.x2.shared.b16 {%0,%1}, [%2];" \
                 : "=r"(R0),"=r"(R1) : "r"(ADDR))
#define STS64V(A, R0, R1) \
    asm volatile("st.shared.v2.b32 [%0], {%1,%2};" :: "r"(A), "r"(R0), "r"(R1) : "memory")

__device__ __forceinline__ void mma_bf16(float* c, const uint32_t* a, const uint32_t* b) {
    asm volatile(
        "mma.sync.aligned.m16n8k16.row.col.f32.bf16.bf16.f32 "
        "{%0,%1,%2,%3}, {%4,%5,%6,%7}, {%8,%9}, {%0,%1,%2,%3};"
        : "+f"(c[0]), "+f"(c[1]), "+f"(c[2]), "+f"(c[3])
        : "r"(a[0]), "r"(a[1]), "r"(a[2]), "r"(a[3]), "r"(b[0]), "r"(b[1]));
}

__device__ __forceinline__ void split_bf16(float v, __nv_bfloat16& hi, __nv_bfloat16& lo) {
    hi = __float2bfloat16(v);
    lo = __float2bfloat16(v - __bfloat162float(hi));
}
__device__ __forceinline__ uint32_t pack2(__nv_bfloat16 a, __nv_bfloat16 b) {
    return (uint32_t)__bfloat16_as_ushort(a) | ((uint32_t)__bfloat16_as_ushort(b) << 16);
}

// ---------------- 1. prep: w1 [0,2048) 2 rows/warp | w2split [2048,2624) | bias [2624,2752) ----
__global__ __launch_bounds__(256) void k_prep(
        const float* __restrict__ meta, const float* __restrict__ w1w,
        const float* __restrict__ w1b, const float* __restrict__ w2w,
        const float* __restrict__ blw, const float* __restrict__ blb) {
    __shared__ float4 sm4[256];
    int bid = blockIdx.x;
    if (bid < 2048) {
        // ---- hyper stage 1: 2 rows per warp, 4 float4 loads in flight, lighter regs ----
        if (threadIdx.x < 256) sm4[threadIdx.x] = ((const float4*)meta)[threadIdx.x];
        __syncthreads();
        int warp = (bid * 256 + threadIdx.x) >> 5;   // 0..16383
        int gw0 = warp * 2;
        int lane = threadIdx.x & 31;
        float4 wv[2][2];
        #pragma unroll
        for (int r = 0; r < 2; r++) {
            const float4* row = (const float4*)(w1w + (size_t)(gw0 + r) * 256);
            wv[r][0] = row[lane];
            wv[r][1] = row[lane + 32];
        }
        float acc[2][4];
        #pragma unroll
        for (int bb = 0; bb < 4; bb++) {
            float4 m0 = sm4[bb * 64 + lane], m1 = sm4[bb * 64 + lane + 32];
            #pragma unroll
            for (int r = 0; r < 2; r++) {
                acc[r][bb] = wv[r][0].x * m0.x + wv[r][0].y * m0.y
                           + wv[r][0].z * m0.z + wv[r][0].w * m0.w
                           + wv[r][1].x * m1.x + wv[r][1].y * m1.y
                           + wv[r][1].z * m1.z + wv[r][1].w * m1.w;
            }
        }
        #pragma unroll
        for (int s = 16; s > 0; s >>= 1)
            #pragma unroll
            for (int r = 0; r < 2; r++)
                #pragma unroll
                for (int bb = 0; bb < 4; bb++)
                    acc[r][bb] += __shfl_xor_sync(~0u, acc[r][bb], s);
        if (lane < 2) {
            int r = lane;
            int gw = gw0 + r;
            float bbias = w1b[gw];
            #pragma unroll
            for (int bb = 0; bb < 4; bb++) {
                __nv_bfloat16 hi, lo;
                split_bf16(acc[r][bb] + bbias, hi, lo);
                d_t1hi[bb * 32768 + gw] = hi;
                d_t1lo[bb * 32768 + gw] = lo;
            }
        }
    } else if (bid < 2624) {
        // ---- w2 split, vectorized ----
        int idx = (bid - 2048) * 1024 + threadIdx.x * 4;
        float4 v = *(const float4*)(w2w + idx);
        __nv_bfloat16 h0, l0, h1, l1, h2, l2, h3, l3;
        split_bf16(v.x, h0, l0); split_bf16(v.y, h1, l1);
        split_bf16(v.z, h2, l2); split_bf16(v.w, h3, l3);
        uint2 hv = make_uint2(pack2(h0, h1), pack2(h2, h3));
        uint2 lv = make_uint2(pack2(l0, l1), pack2(l2, l3));
        *(uint2*)(d_w2hi + idx) = hv;
        *(uint2*)(d_w2lo + idx) = lv;
    } else {
        int gw = ((bid - 2624) * 256 + threadIdx.x) >> 5;  // 0..1023
        int lane = threadIdx.x & 31;
        int b = gw >> 8, o = gw & 255;
        const float* row = blw + o * 256;
        const float* m = meta + b * 256;
        float a = 0.f;
        #pragma unroll
        for (int k = lane; k < 256; k += 32) a += row[k] * m[k];
        #pragma unroll
        for (int s = 16; s > 0; s >>= 1) a += __shfl_xor_sync(~0u, a, s);
        if (lane == 0) d_bm[gw] = a + blb[o];
    }
}

// ---------------- 2. merged: hyper2 GEMM (blocks 0..143) + offset conv (144..207) ----
#define H2P 80
#define H2A (128 * H2P)                    // 10240 per A component
#define H2B (64 * H2P)                     // 5120 per B component
#define H2STG (2 * H2A + 2 * H2B)          // 30720
#define H2SMEM (2 * H2STG)                 // 61440
__global__ __launch_bounds__(256, 1) void k_h2off(const float* __restrict__ w2b,
                                                  const float* __restrict__ mio,
                                                  const float* __restrict__ pw,
                                                  const float* __restrict__ pb) {
    extern __shared__ char smb[];
    int bidx = blockIdx.x;
    if (bidx >= 144) {
        // ---- offset conv + masked sampling indices/weights ----
        float* sw = (float*)smb;            // 162 floats
        float* sb = sw + 162;               // 18 floats
        int sub = bidx - 144;               // 0..63
        int b = sub >> 4;
        int hw = (sub & 15) * 256 + threadIdx.x;
        if (threadIdx.x < 162) sw[threadIdx.x] = pw[threadIdx.x];
        if (threadIdx.x < 18)  sb[threadIdx.x] = pb[threadIdx.x];
        __syncthreads();
        int h = hw >> 6, w = hw & 63;
        const float* plane = mio + b * 4096;
        float v[9];
        #pragma unroll
        for (int kh = 0; kh < 3; kh++)
            #pragma unroll
            for (int kw = 0; kw < 3; kw++) {
                int hi = h - 1 + kh, wi = w - 1 + kw;
                v[kh * 3 + kw] = (hi >= 0 && hi < 64 && wi >= 0 && wi < 64) ? plane[hi * 64 + wi] : 0.f;
            }
        #pragma unroll
        for (int n = 0; n < 9; n++) {
            float offx = sb[n], offy = sb[9 + n];
            #pragma unroll
            for (int t = 0; t < 9; t++) {
                offx += v[t] * sw[n * 9 + t];
                offy += v[t] * sw[(9 + n) * 9 + t];
            }
            float px = (float)(h + 1) + (float)(n / 3 - 1) + offx;
            float py = (float)(w + 1) + (float)(n % 3 - 1) + offy;
            float fx = floorf(px), fy = floorf(py);
            int xlt = min(max((int)fx, 0), 65);
            int xrb = min(max((int)fx + 1, 0), 65);
            int ylt = min(max((int)fy, 0), 65);
            int yrb = min(max((int)fy + 1, 0), 65);
            float pcx = fminf(fmaxf(px, 0.f), 65.f);
            float pcy = fminf(fmaxf(py, 0.f), 65.f);
            float glt = (1.f + ((float)xlt - pcx)) * (1.f + ((float)ylt - pcy));
            float grb = (1.f - ((float)xrb - pcx)) * (1.f - ((float)yrb - pcy));
            float glb = (1.f + ((float)xlt - pcx)) * (1.f - ((float)yrb - pcy));
            float grt = (1.f - ((float)xrb - pcx)) * (1.f + ((float)ylt - pcy));
            int4 id;
            float4 g;
            #define MASK(X, Y, G, IDX, GO) { \
                bool vv = ((X) >= 1) && ((X) <= 64) && ((Y) >= 1) && ((Y) <= 64); \
                IDX = vv ? (((X) - 1) * 64 + ((Y) - 1)) : 0; \
                GO = vv ? (G) : 0.f; }
            MASK(xlt, ylt, glt, id.x, g.x);
            MASK(xrb, yrb, grb, id.y, g.y);
            MASK(xlt, yrb, glb, id.z, g.z);
            MASK(xrb, ylt, grt, id.w, g.w);
            #undef MASK
            int base = ((b * 9 + n) * HW4 + hw) * 4;
            *(int4*)(d_idx + base) = id;
            *(float4*)(d_gw + base) = g;
        }
        return;
    }

    // ---- hyper2 bf16x3 GEMM 512x2304x256 -> A hi/lo (k = n*128 + c) ----
    uint32_t s0 = smem_u32(smb);
    int tid = threadIdx.x, wid = tid >> 5, lane = tid & 31;
    int row0 = (bidx / 36) * 128;
    int col0 = (bidx % 36) * 64;

    auto load_stage = [&](int stage, int k0) {
        uint32_t sa = s0 + stage * H2STG;
        #pragma unroll
        for (int i = 0; i < 2; i++) {
            int l = tid + i * 256;
            int r = l >> 2, seg = l & 3;
            CP_ASYNC16(sa + r * H2P + seg * 16,
                       d_t1hi + (size_t)(row0 + r) * 256 + k0 + seg * 8);
        }
        #pragma unroll
        for (int i = 0; i < 2; i++) {
            int l = tid + i * 256;
            int r = l >> 2, seg = l & 3;
            CP_ASYNC16(sa + H2A + r * H2P + seg * 16,
                       d_t1lo + (size_t)(row0 + r) * 256 + k0 + seg * 8);
        }
        {
            int r = tid >> 2, seg = tid & 3;
            CP_ASYNC16(sa + 2 * H2A + r * H2P + seg * 16,
                       d_w2hi + (size_t)(col0 + r) * 256 + k0 + seg * 8);
            CP_ASYNC16(sa + 2 * H2A + H2B + r * H2P + seg * 16,
                       d_w2lo + (size_t)(col0 + r) * 256 + k0 + seg * 8);
        }
    };

    float acc[4][2][4];
    #pragma unroll
    for (int i = 0; i < 4; i++)
        #pragma unroll
        for (int j = 0; j < 2; j++)
            #pragma unroll
            for (int q = 0; q < 4; q++) acc[i][j][q] = 0.f;

    load_stage(0, 0);
    CP_COMMIT();

    int mwarp = (wid & 1) * 64;
    int nwarp = (wid >> 1) * 16;
    int grp = lane >> 2, tig = lane & 3;
    uint32_t aRow = (uint32_t)(mwarp + (lane & 15)) * H2P + (((uint32_t)lane >> 4) << 4);
    int lB = lane & 15;
    uint32_t bRow = (uint32_t)(nwarp + (lB & 7)) * H2P + ((((uint32_t)lB >> 3) & 1) << 4);

    for (int it = 0; it < 8; it++) {
        int cur = it & 1;
        if (it + 1 < 8) {
            load_stage(1 - cur, (it + 1) * 32);
            CP_COMMIT();
            CP_WAIT(1);
        } else {
            CP_WAIT(0);
        }
        __syncthreads();
        uint32_t base = s0 + cur * H2STG;
        #pragma unroll
        for (int s = 0; s < 2; s++) {
            uint32_t kof = (uint32_t)s * 32;
            uint32_t bh[2][2], bl[2][2];
            #pragma unroll
            for (int nt = 0; nt < 2; nt++) {
                uint32_t ab = base + 2 * H2A + bRow + nt * (8 * H2P) + kof;
                LDSM_X2(bh[nt][0], bh[nt][1], ab);
                LDSM_X2(bl[nt][0], bl[nt][1], ab + H2B);
            }
            #pragma unroll
            for (int mt = 0; mt < 4; mt++) {
                uint32_t aa = base + aRow + mt * (16 * H2P) + kof;
                uint32_t ah[4], al[4];
                LDSM_X4(ah[0], ah[1], ah[2], ah[3], aa);
                LDSM_X4(al[0], al[1], al[2], al[3], aa + H2A);
                #pragma unroll
                for (int nt = 0; nt < 2; nt++) {
                    mma_bf16(acc[mt][nt], ah, bh[nt]);
                    mma_bf16(acc[mt][nt], ah, bl[nt]);
                    mma_bf16(acc[mt][nt], al, bh[nt]);
                }
            }
        }
        __syncthreads();
    }

    // epilogue: stage tile in smem, coalesced hi/lo store
    __syncthreads();
    float* Cs = (float*)smb;               // [128][68]
    #pragma unroll
    for (int mt = 0; mt < 4; mt++)
        #pragma unroll
        for (int nt = 0; nt < 2; nt++)
            #pragma unroll
            for (int q = 0; q < 4; q++) {
                int rloc = mwarp + mt * 16 + grp + ((q >> 1) ? 8 : 0);
                int cloc = nwarp + nt * 8 + tig * 2 + (q & 1);
                Cs[rloc * 68 + cloc] = acc[mt][nt][q];
            }
    __syncthreads();
    {
        int j = tid >> 2, q4 = tid & 3;
        int jj = col0 + j;
        int o = jj / 9, n = jj - o * 9;
        int bb = row0 >> 7;
        float wbv = w2b[jj];
        size_t dstoff = ((size_t)(bb * 256 + o)) * CN + n * 128 + q4 * 32;
        #pragma unroll
        for (int cl = 0; cl < 32; cl += 2) {
            float v0 = Cs[(q4 * 32 + cl) * 68 + j] + wbv;
            float v1 = Cs[(q4 * 32 + cl + 1) * 68 + j] + wbv;
            __nv_bfloat16 h0, l0, h1, l1;
            split_bf16(v0, h0, l0);
            split_bf16(v1, h1, l1);
            *(uint32_t*)(d_Ahi + dstoff + cl) = pack2(h0, h1);
            *(uint32_t*)(d_Alo + dstoff + cl) = pack2(l0, l1);
        }
    }
}

// ---------------- 3. fused gather + bf16x3 GEMM + LSTM gates (hoisted gather issue) ----
#define KC 32
#define APITCH 40
#define AHB (256 * APITCH * 2)             // 20480
#define BHB (128 * APITCH * 2)             // 10240
#define OFF_AL AHB
#define OFF_BH (2 * AHB)
#define OFF_BL (2 * AHB + BHB)
#define STG (2 * AHB + 2 * BHB)            // 61440
#define NSTAGE 3
#define IDXOFF (NSTAGE * STG)              // 184320
#define GWOFF  (IDXOFF + 18432)
#define GSMEM  (GWOFF + 18432)             // 221184

__global__ __launch_bounds__(512, 1) void k_gemm_mma(const float* __restrict__ inp,
                                                     const float* __restrict__ hcur,
                                                     const float* __restrict__ ccur,
                                                     float* __restrict__ out) {
    extern __shared__ char smb[];
    uint32_t s0 = smem_u32(smb);
    int tid = threadIdx.x, wid = tid >> 5, lane = tid & 31;
    int b = blockIdx.y;
    int hw0 = blockIdx.x * 128;

    const __nv_bfloat16* Ahi = d_Ahi + (size_t)b * 256 * CN;
    const __nv_bfloat16* Alo = d_Alo + (size_t)b * 256 * CN;
    const float* ibase = inp + (size_t)b * 64 * 4096;
    const float* hbase = hcur + (size_t)b * 64 * 4096;

    auto loadA = [&](int stage, int k0) {
        uint32_t sa = s0 + stage * STG;
        #pragma unroll
        for (int i = 0; i < 2; i++) {
            int l = tid + i * 512;
            int r = l >> 2, seg = l & 3;
            CP_ASYNC16(sa + r * 80 + seg * 16, Ahi + (size_t)r * CN + k0 + seg * 8);
        }
        #pragma unroll
        for (int i = 0; i < 2; i++) {
            int l = tid + i * 512;
            int r = l >> 2, seg = l & 3;
            CP_ASYNC16(sa + OFF_AL + r * 80 + seg * 16, Alo + (size_t)r * CN + k0 + seg * 8);
        }
    };

    int hwl = tid >> 2;
    int cg = (tid & 3) << 3;

    auto issue_half = [&](int ch, int hf, float* L) {
        int n = ch >> 2, c0 = (ch & 3) << 5;
        int c = c0 + cg + hf * 4;
        int4 id = ((const int4*)(smb + IDXOFF))[n * 128 + hwl];
        const float* pl0 = (c < 64) ? (ibase + (size_t)c * 4096)
                                    : (hbase + (size_t)(c - 64) * 4096);
        #pragma unroll
        for (int j = 0; j < 4; j++) {
            const float* pl = pl0 + (size_t)j * 4096;
            L[j * 4 + 0] = pl[id.x];
            L[j * 4 + 1] = pl[id.y];
            L[j * 4 + 2] = pl[id.z];
            L[j * 4 + 3] = pl[id.w];
        }
    };
    auto store_half = [&](int stage, int ch, int hf, const float* L) {
        int n = ch >> 2;
        float4 g = ((const float4*)(smb + GWOFF))[n * 128 + hwl];
        float v[4];
        #pragma unroll
        for (int j = 0; j < 4; j++)
            v[j] = g.x * L[j * 4] + g.y * L[j * 4 + 1] + g.z * L[j * 4 + 2] + g.w * L[j * 4 + 3];
        __nv_bfloat16 h0, l0, h1, l1, h2, l2, h3, l3;
        split_bf16(v[0], h0, l0); split_bf16(v[1], h1, l1);
        split_bf16(v[2], h2, l2); split_bf16(v[3], h3, l3);
        uint32_t ba = s0 + stage * STG + OFF_BH + hwl * 80 + (cg + hf * 4) * 2;
        STS64V(ba, pack2(h0, h1), pack2(h2, h3));
        STS64V(ba + BHB, pack2(l0, l1), pack2(l2, l3));
    };

    for (int i = tid; i < 1152; i += 512) {
        int n = i >> 7, hh = i & 127;
        int gb = ((b * 9 + n) * HW4 + hw0 + hh) * 4;
        ((int4*)(smb + IDXOFF))[i] = *(const int4*)(d_idx + gb);
        ((float4*)(smb + GWOFF))[i] = *(const float4*)(d_gw + gb);
    }
    loadA(0, 0); CP_COMMIT();
    loadA(1, KC); CP_COMMIT();
    __syncthreads();
    {
        float L[16];
        issue_half(0, 0, L); store_half(0, 0, 0, L);
        issue_half(0, 1, L); store_half(0, 0, 1, L);
        issue_half(1, 0, L); store_half(1, 1, 0, L);
        issue_half(1, 1, L); store_half(1, 1, 1, L);
    }

    float acc[4][4][4];
    #pragma unroll
    for (int i = 0; i < 4; i++)
        #pragma unroll
        for (int j = 0; j < 4; j++)
            #pragma unroll
            for (int q = 0; q < 4; q++) acc[i][j][q] = 0.f;

    int mwarp = (wid & 3) * 64;
    int nwarp = (wid >> 2) * 32;
    int grp = lane >> 2, tig = lane & 3;
    uint32_t aRow = (uint32_t)(mwarp + (lane & 15)) * 80 + (((uint32_t)lane >> 4) << 4);
    uint32_t bRow4 = (uint32_t)((lane & 7) + ((lane & 16) >> 1)) * 80 + ((lane & 8) << 1);

    for (int it = 0; it < 36; it++) {
        int cur = it % NSTAGE;
        int pch = it + 2;
        bool hasP = pch < 36;
        int pst = pch % NSTAGE;
        float L[16];
        if (hasP) issue_half(pch, 0, L);   // register-only; overlaps barrier + s0 MMA
        if (it + 1 < 36) { CP_WAIT(1); } else { CP_WAIT(0); }
        __syncthreads();
        if (hasP) {
            loadA(pst, pch * KC);
            CP_COMMIT();
        }
        uint32_t base = s0 + cur * STG;
        // ---- MMA s = 0 ----
        {
            uint32_t kof = 0;
            uint32_t bh[4][2], bl[4][2];
            #pragma unroll
            for (int p = 0; p < 2; p++) {
                uint32_t ab = base + OFF_BH + (uint32_t)(nwarp + p * 16) * 80 + bRow4 + kof;
                LDSM_X4(bh[2 * p][0], bh[2 * p][1], bh[2 * p + 1][0], bh[2 * p + 1][1], ab);
                LDSM_X4(bl[2 * p][0], bl[2 * p][1], bl[2 * p + 1][0], bl[2 * p + 1][1], ab + BHB);
            }
            #pragma unroll
            for (int mt = 0; mt < 4; mt++) {
                uint32_t aa = base + aRow + mt * (16 * 80) + kof;
                uint32_t ah[4], al[4];
                LDSM_X4(ah[0], ah[1], ah[2], ah[3], aa);
                LDSM_X4(al[0], al[1], al[2], al[3], aa + AHB);
                #pragma unroll
                for (int nt = 0; nt < 4; nt++) {
                    mma_bf16(acc[mt][nt], ah, bh[nt]);
                    mma_bf16(acc[mt][nt], ah, bl[nt]);
                    mma_bf16(acc[mt][nt], al, bh[nt]);
                }
            }
        }
        if (hasP) {
            store_half(pst, pch, 0, L);
            issue_half(pch, 1, L);
        }
        // ---- MMA s = 1 ----
        {
            uint32_t kof = 32;
            uint32_t bh[4][2], bl[4][2];
            #pragma unroll
            for (int p = 0; p < 2; p++) {
                uint32_t ab = base + OFF_BH + (uint32_t)(nwarp + p * 16) * 80 + bRow4 + kof;
                LDSM_X4(bh[2 * p][0], bh[2 * p][1], bh[2 * p + 1][0], bh[2 * p + 1][1], ab);
                LDSM_X4(bl[2 * p][0], bl[2 * p][1], bl[2 * p + 1][0], bl[2 * p + 1][1], ab + BHB);
            }
            #pragma unroll
            for (int mt = 0; mt < 4; mt++) {
                uint32_t aa = base + aRow + mt * (16 * 80) + kof;
                uint32_t ah[4], al[4];
                LDSM_X4(ah[0], ah[1], ah[2], ah[3], aa);
                LDSM_X4(al[0], al[1], al[2], al[3], aa + AHB);
                #pragma unroll
                for (int nt = 0; nt < 4; nt++) {
                    mma_bf16(acc[mt][nt], ah, bh[nt]);
                    mma_bf16(acc[mt][nt], ah, bl[nt]);
                    mma_bf16(acc[mt][nt], al, bh[nt]);
                }
            }
        }
        if (hasP) store_half(pst, pch, 1, L);
    }
    __syncthreads();

    // ---- stage C tile (with bias) into smem, then fused LSTM gates ----
    float* Cs = (float*)smb;               // [256][132]
    const float* bmp = d_bm + b * 256;
    #pragma unroll
    for (int mt = 0; mt < 4; mt++) {
        int row = mwarp + mt * 16 + grp;
        float bz0 = bmp[row], bz1 = bmp[row + 8];
        #pragma unroll
        for (int nt = 0; nt < 4; nt++) {
            int col = nwarp + nt * 8 + tig * 2;
            Cs[row * 132 + col]           = acc[mt][nt][0] + bz0;
            Cs[row * 132 + col + 1]       = acc[mt][nt][1] + bz0;
            Cs[(row + 8) * 132 + col]     = acc[mt][nt][2] + bz1;
            Cs[(row + 8) * 132 + col + 1] = acc[mt][nt][3] + bz1;
        }
    }
    __syncthreads();
    #pragma unroll
    for (int q = 0; q < 16; q++) {
        int lin = q * 512 + tid;           // < 8192
        int hid = lin >> 7, hw = lin & 127;
        float ci = Cs[hid * 132 + hw];
        float cf = Cs[(hid + 64) * 132 + hw];
        float co = Cs[(hid + 128) * 132 + hw];
        float cg2 = Cs[(hid + 192) * 132 + hw];
        float ig = 1.f / (1.f + expf(-ci));
        float fg = 1.f / (1.f + expf(-cf));
        float og = 1.f / (1.f + expf(-co));
        float gg = tanhf(cg2);
        int g = (b * 64 + hid) * HW4 + hw0 + hw;
        float cn = fg * ccur[g] + ig * gg;
        float hn = og * tanhf(cn);
        out[g] = hn;
        out[1048576 + g] = cn;
    }
}

// ---------------- launch ----------------
extern "C" void kernel_launch(void* const* d_in, const int* in_sizes, int n_in,
                              void* d_out, int out_size) {
    const float* inp  = (const float*)d_in[0];
    const float* hcur = (const float*)d_in[1];
    const float* ccur = (const float*)d_in[2];
    const float* meta = (const float*)d_in[3];
    const float* mio  = (const float*)d_in[4];
    const float* w1w  = (const float*)d_in[5];
    const float* w1b  = (const float*)d_in[6];
    const float* w2w  = (const float*)d_in[7];
    const float* w2b  = (const float*)d_in[8];
    const float* blw  = (const float*)d_in[9];
    const float* blb  = (const float*)d_in[10];
    const float* pw   = (const float*)d_in[11];
    const float* pb   = (const float*)d_in[12];
    float* out = (float*)d_out;

    cudaFuncSetAttribute(k_h2off, cudaFuncAttributeMaxDynamicSharedMemorySize, H2SMEM);
    cudaFuncSetAttribute(k_gemm_mma, cudaFuncAttributeMaxDynamicSharedMemorySize, GSMEM);

    k_prep    <<<2752, 256>>>(meta, w1w, w1b, w2w, blw, blb);
    k_h2off   <<<208, 256, H2SMEM>>>(w2b, mio, pw, pb);
    k_gemm_mma<<<dim3(32, 4), 512, GSMEM>>>(inp, hcur, ccur, out);
}